// round 14
// baseline (speedup 1.0000x reference)
#include <cuda_runtime.h>
#include <cuda_bf16.h>
#include <cstdint>

// WeightedSumSessEmbedding: sparse COO [16384 x 1M] @ emb[1M x 64]
// NNZ=819200, row_idx sorted. Inputs: row_idx[i32], col_idx[i32],
// data[f32], num_ids[i32 scalar], embeddings[f32 1M*64]. Output f32 [16384*64].
//
// R13 half-warp float4 scheme (one LDG.128 gathers 2 nnz) + software-
// pipelined ping-pong batches: batch b+1's 8 LDG.128s are issued BEFORE
// batch b is consumed, so each warp keeps 8-16 gathers continuously in
// flight (no per-batch drain bubble).

#define EMB_DIM 64
#define CHUNK 64                       // nnz per warp
#define THREADS 256                    // 8 warps per block
#define WARPS_PB (THREADS / 32)
#define NNZ_PB (WARPS_PB * CHUNK)      // 512 nnz per block
#define PUNROLL 8                      // LDG.128s per batch = 16 nnz
#define NB (CHUNK / (2 * PUNROLL))     // 4 batches per chunk

__device__ __forceinline__ void red_add_v4(float* p, float4 v)
{
    asm volatile("red.global.add.v4.f32 [%0], {%1, %2, %3, %4};"
                 :: "l"(p), "f"(v.x), "f"(v.y), "f"(v.z), "f"(v.w) : "memory");
}

__global__ void __launch_bounds__(THREADS, 3)   // 84-reg budget: 2 batches live
weighted_seg_sum_kernel(const int* __restrict__ row_idx,
                        const int* __restrict__ col_idx,
                        const float* __restrict__ data,
                        const float* __restrict__ emb,
                        float* __restrict__ out,
                        int nnz)
{
    __shared__ int   s_row[NNZ_PB];
    __shared__ int   s_col[NNZ_PB];
    __shared__ float s_w[NNZ_PB];

    const int lane     = threadIdx.x & 31;
    const int half     = lane >> 4;           // which nnz of each pair
    const int sub      = lane & 15;           // float4 slot within the row
    const int wl       = threadIdx.x >> 5;
    const int blk_base = blockIdx.x * NNZ_PB;

    // ---- cooperative index staging: 512 x 12B, fully coalesced ----
    #pragma unroll
    for (int t = threadIdx.x; t < NNZ_PB; t += THREADS) {
        const int g = blk_base + t;
        if (g < nnz) {
            s_row[t] = row_idx[g];
            s_col[t] = col_idx[g];
            s_w[t]   = data[g];
        }
    }
    __syncthreads();

    const int start = blk_base + wl * CHUNK;
    if (start >= nnz) return;
    const int n  = min(CHUNK, nnz - start);
    const int l0 = wl * CHUNK;

    // emb viewed as float4: one row = 16 float4s; lane sub owns dims [4*sub..4*sub+3].
    const float4* __restrict__ emb4 = reinterpret_cast<const float4*>(emb);

    float4 acc = make_float4(0.0f, 0.0f, 0.0f, 0.0f);
    int cur_row = s_row[l0 + min(half, n - 1)];

    #define FLUSH()                                                          \
        do {                                                                 \
            red_add_v4(out + (size_t)cur_row * EMB_DIM + 4 * sub, acc);      \
            acc.x = 0.0f; acc.y = 0.0f; acc.z = 0.0f; acc.w = 0.0f;          \
        } while (0)

    #define STEP(_r, _w, _e)                                                 \
        do {                                                                 \
            if ((_r) != cur_row) { FLUSH(); cur_row = (_r); }                \
            acc.x = fmaf((_w), (_e).x, acc.x);                               \
            acc.y = fmaf((_w), (_e).y, acc.y);                               \
            acc.z = fmaf((_w), (_e).z, acc.z);                               \
            acc.w = fmaf((_w), (_e).w, acc.w);                               \
        } while (0)

    if (n == CHUNK) {
        // ---- fully pipelined path (all blocks: NNZ is a multiple of 512) ----
        float4 ev[2][PUNROLL];

        // Prologue: issue batch 0's gathers.
        #pragma unroll
        for (int j = 0; j < PUNROLL; ++j)
            ev[0][j] = __ldg(emb4 +
                (size_t)s_col[l0 + 2 * j + half] * 16 + sub);

        #pragma unroll
        for (int b = 0; b < NB; ++b) {
            const int cur = b & 1;
            const int nxt = cur ^ 1;

            // Issue batch b+1 BEFORE consuming batch b.
            if (b + 1 < NB) {
                const int nb_base = l0 + (b + 1) * 2 * PUNROLL;
                #pragma unroll
                for (int j = 0; j < PUNROLL; ++j)
                    ev[nxt][j] = __ldg(emb4 +
                        (size_t)s_col[nb_base + 2 * j + half] * 16 + sub);
            }

            // Consume batch b.
            const int cb_base = l0 + b * 2 * PUNROLL;
            #pragma unroll
            for (int j = 0; j < PUNROLL; ++j) {
                const int   rv = s_row[cb_base + 2 * j + half];
                const float wv = s_w[cb_base + 2 * j + half];
                STEP(rv, wv, ev[cur][j]);
            }
        }
    } else {
        // ---- generic tail path (partial chunk) ----
        for (int li = l0; li < l0 + n; li += 2) {
            const int  idx   = li + half;
            const bool valid = idx < l0 + n;
            const int   cv = valid ? s_col[idx] : 0;
            const float wv = valid ? s_w[idx]   : 0.0f;
            const int   rv = valid ? s_row[idx] : cur_row;
            const float4 evs = __ldg(emb4 + (size_t)cv * 16 + sub);
            STEP(rv, wv, evs);
        }
    }

    FLUSH();

    #undef STEP
    #undef FLUSH
}

extern "C" void kernel_launch(void* const* d_in, const int* in_sizes, int n_in,
                              void* d_out, int out_size)
{
    const int*   row_idx = (const int*)  d_in[0];
    const int*   col_idx = (const int*)  d_in[1];
    const float* data    = (const float*)d_in[2];
    const float* emb     = (const float*)d_in[4];
    float*       out     = (float*)d_out;

    const int nnz = in_sizes[0];

    cudaMemsetAsync(out, 0, (size_t)out_size * sizeof(float));

    const int blocks = (nnz + NNZ_PB - 1) / NNZ_PB;
    weighted_seg_sum_kernel<<<blocks, THREADS>>>(
        row_idx, col_idx, data, emb, out, nnz);
}